// round 9
// baseline (speedup 1.0000x reference)
#include <cuda_runtime.h>

#define BB      16384
#define NSITES  784
#define DD      8
#define OO      10
#define LABEL   392
#define LLEFT   391   // sites 1..391
#define LRIGHT  390   // sites 393..782 (walked reversed, transposed)
#define NPAIR   74    // CTAs per side
#define SLOTS_PER_CTA 256

typedef unsigned long long u64;

// ---------------- packed f32x2 helpers ----------------
__device__ __forceinline__ u64 pk2(float a, float b) {
    u64 r; asm("mov.b64 %0, {%1, %2};" : "=l"(r) : "f"(a), "f"(b)); return r;
}
__device__ __forceinline__ void upk2(float& a, float& b, u64 r) {
    asm("mov.b64 {%0, %1}, %2;" : "=f"(a), "=f"(b) : "l"(r));
}
__device__ __forceinline__ u64 fma2(u64 a, u64 b, u64 c) {
    u64 d; asm("fma.rn.f32x2 %0, %1, %2, %3;" : "=l"(d) : "l"(a), "l"(b), "l"(c)); return d;
}
__device__ __forceinline__ u64 mul2(u64 a, u64 b) {
    u64 d; asm("mul.rn.f32x2 %0, %1, %2;" : "=l"(d) : "l"(a), "l"(b)); return d;
}

// ---------------- scratch ----------------
__device__ __align__(16) float g_WL[LLEFT * 128];     // per step: A (64) | C (64)
__device__ __align__(16) float g_WR[LRIGHT * 128];    // transposed + reversed
__device__ __align__(8)  float g_Alab[DD * DD * OO];
__device__ __align__(8)  float g_Clab[DD * DD * OO];
__device__ float g_w0c[16];
__device__ float g_wlastc[16];
__device__ __align__(16) float g_vleft[BB * 8];
__device__ __align__(16) float g_u[BB * 8];
__device__ unsigned g_flag[NPAIR];

// ---------------- weight prep ----------------
__global__ void prep_weights(const float* __restrict__ wl,
                             const float* __restrict__ wlab,
                             const float* __restrict__ wr,
                             const float* __restrict__ w0,
                             const float* __restrict__ wlast) {
    int idx = blockIdx.x * blockDim.x + threadIdx.x;
    if (idx < LLEFT * 64) {
        int s = idx >> 6; int r = idx & 63; int d = r >> 3; int e = r & 7;
        float a = wl[((s * 8 + d) * 2 + 0) * 8 + e];
        float b = wl[((s * 8 + d) * 2 + 1) * 8 + e];
        g_WL[s * 128 + d * 8 + e] = a;
        g_WL[s * 128 + 64 + d * 8 + e] = b - a;
        return;
    }
    idx -= LLEFT * 64;
    if (idx < LRIGHT * 64) {           // step t uses site (782 - t), transposed
        int t = idx >> 6; int r = idx & 63; int i = r >> 3; int j = r & 7;
        int site_local = (LRIGHT - 1) - t;
        float a = wr[((site_local * 8 + j) * 2 + 0) * 8 + i];
        float b = wr[((site_local * 8 + j) * 2 + 1) * 8 + i];
        g_WR[t * 128 + i * 8 + j] = a;
        g_WR[t * 128 + 64 + i * 8 + j] = b - a;
        return;
    }
    idx -= LRIGHT * 64;
    if (idx < DD * DD * OO) {
        int o = idx % OO; int de = idx / OO; int e = de & 7; int d = de >> 3;
        float a = wlab[((d * 2 + 0) * 8 + e) * OO + o];
        float b = wlab[((d * 2 + 1) * 8 + e) * OO + o];
        g_Alab[(d * 8 + e) * OO + o] = a;
        g_Clab[(d * 8 + e) * OO + o] = b - a;
        return;
    }
    idx -= DD * DD * OO;
    if (idx < 8) { g_w0c[idx] = w0[idx]; g_w0c[8 + idx] = w0[8 + idx] - w0[idx]; return; }
    idx -= 8;
    if (idx < 8) {
        g_wlastc[idx]     = wlast[idx * 2 + 0];
        g_wlastc[8 + idx] = wlast[idx * 2 + 1] - wlast[idx * 2 + 0];
        return;
    }
    idx -= 8;
    if (idx < NPAIR) g_flag[idx] = 0;
}

// ---------------- one site step, single row (e-packed), mul2-init ----------------
__device__ __forceinline__ void site_step(const float* __restrict__ wsite,
                                          float (&v)[8], float pc) {
    const ulonglong2* __restrict__ w2 = (const ulonglong2*)wsite;
    u64 A0, A1, A2, A3, C0, C1, C2, C3;
    {
        u64 vd = pk2(v[0], v[0]);
        ulonglong2 qa = w2[0], qb = w2[1];
        ulonglong2 qc = w2[16], qd = w2[17];
        A0 = mul2(vd, qa.x); A1 = mul2(vd, qa.y);
        A2 = mul2(vd, qb.x); A3 = mul2(vd, qb.y);
        C0 = mul2(vd, qc.x); C1 = mul2(vd, qc.y);
        C2 = mul2(vd, qd.x); C3 = mul2(vd, qd.y);
    }
    #pragma unroll
    for (int i = 1; i < 8; i++) {
        u64 vd = pk2(v[i], v[i]);
        ulonglong2 qa = w2[2 * i], qb = w2[2 * i + 1];
        ulonglong2 qc = w2[16 + 2 * i], qd = w2[16 + 2 * i + 1];
        A0 = fma2(vd, qa.x, A0); A1 = fma2(vd, qa.y, A1);
        A2 = fma2(vd, qb.x, A2); A3 = fma2(vd, qb.y, A3);
        C0 = fma2(vd, qc.x, C0); C1 = fma2(vd, qc.y, C1);
        C2 = fma2(vd, qd.x, C2); C3 = fma2(vd, qd.y, C3);
    }
    u64 p2 = pk2(pc, pc);
    A0 = fma2(p2, C0, A0); A1 = fma2(p2, C1, A1);
    A2 = fma2(p2, C2, A2); A3 = fma2(p2, C3, A3);
    upk2(v[0], v[1], A0); upk2(v[2], v[3], A1);
    upk2(v[4], v[5], A2); upk2(v[6], v[7], A3);
}

// ---------------- label combine for one row ----------------
__device__ __forceinline__ void label_row(const u64* __restrict__ sA,
                                          const u64* __restrict__ sC,
                                          const float (&vl)[8], const float (&uu)[8],
                                          float p, float* __restrict__ out, int row) {
    const u64 p2 = pk2(p, p);
    u64 acc[5] = {0, 0, 0, 0, 0};
    #pragma unroll
    for (int d = 0; d < 8; d++) {
        #pragma unroll
        for (int e = 0; e < 8; e++) {
            const float g = vl[d] * uu[e];
            const u64 g2 = pk2(g, g);
            const u64 gp2 = mul2(g2, p2);
            const int base = (d * 8 + e) * 5;
            #pragma unroll
            for (int k = 0; k < 5; k++) {
                acc[k] = fma2(g2, sA[base + k], acc[k]);
                acc[k] = fma2(gp2, sC[base + k], acc[k]);
            }
        }
    }
    float2* o2 = (float2*)(out + row * OO);
    #pragma unroll
    for (int k = 0; k < 5; k++) {
        float lo, hi; upk2(lo, hi, acc[k]);
        o2[k] = make_float2(lo, hi);
    }
}

// ---------------- fused chain + label kernel: 148 CTAs, 256 thr, 1 row/thread ----------------
__global__ __launch_bounds__(256, 1) void chain_kernel(const float* __restrict__ x,
                                                       float* __restrict__ out) {
    extern __shared__ float sw[];
    __shared__ unsigned s_old;
    const int tid = threadIdx.x;
    const int blk = blockIdx.x;            // 0..147
    const bool isLeft = blk < NPAIR;
    const int pair = isLeft ? blk : blk - NPAIR;

    {   // stage this side's weights
        const float4* g4 = (const float4*)(isLeft ? g_WL : g_WR);
        float4* s4 = (float4*)sw;
        const int n4 = (isLeft ? LLEFT : LRIGHT) * 32;
        for (int i = tid; i < n4; i += 256) s4[i] = g4[i];
    }
    __syncthreads();

    // slot -> row compression: 74*256 = 18944 slots onto 16384 rows (monotone onto)
    const unsigned slot = pair * SLOTS_PER_CTA + tid;
    const int r = (int)((slot * 32u) / 37u);
    const float* px = x + (size_t)r * NSITES;

    float v[8];
    if (isLeft) {
        float4 f = *(const float4*)(px);
        #pragma unroll
        for (int d = 0; d < 8; d++) v[d] = fmaf(f.x, g_w0c[8 + d], g_w0c[d]);
        float4 nf = *(const float4*)(px + 4);
        site_step(sw + 0 * 128, v, f.y);               // site 1
        site_step(sw + 1 * 128, v, f.z);               // site 2
        site_step(sw + 2 * 128, v, f.w);               // site 3
        const float* wp = sw + 3 * 128;
        #pragma unroll 1
        for (int g = 1; g <= 97; g++) {                // sites 4g..4g+3
            f = nf;
            nf = *(const float4*)(px + 4 * g + 4);     // g=97 -> x[392..395], valid
            site_step(wp, v, f.x); wp += 128;
            site_step(wp, v, f.y); wp += 128;
            site_step(wp, v, f.z); wp += 128;
            site_step(wp, v, f.w); wp += 128;
        }
        float4* d0 = (float4*)(g_vleft + r * 8);
        d0[0] = make_float4(v[0], v[1], v[2], v[3]);
        d0[1] = make_float4(v[4], v[5], v[6], v[7]);
    } else {
        float4 f = *(const float4*)(px + 780);         // sites 780..783
        #pragma unroll
        for (int d = 0; d < 8; d++) v[d] = fmaf(f.w, g_wlastc[8 + d], g_wlastc[d]);
        float4 nf = *(const float4*)(px + 776);
        site_step(sw + 0 * 128, v, f.z);               // site 782
        site_step(sw + 1 * 128, v, f.y);               // site 781
        site_step(sw + 2 * 128, v, f.x);               // site 780
        const float* wp = sw + 3 * 128;
        #pragma unroll 1
        for (int m = 0; m < 96; m++) {                 // sites 779-4m .. 776-4m
            f = nf;
            nf = *(const float4*)(px + 772 - 4 * m);   // m=95 -> x[392..395]; never OOB
            site_step(wp, v, f.w); wp += 128;
            site_step(wp, v, f.z); wp += 128;
            site_step(wp, v, f.y); wp += 128;
            site_step(wp, v, f.x); wp += 128;
        }
        f = nf;                                        // x[392..395]: sites 395,394,393
        site_step(wp, v, f.w); wp += 128;
        site_step(wp, v, f.z); wp += 128;
        site_step(wp, v, f.y);
        float4* d0 = (float4*)(g_u + r * 8);
        d0[0] = make_float4(v[0], v[1], v[2], v[3]);
        d0[1] = make_float4(v[4], v[5], v[6], v[7]);
    }

    // ---- handoff: second arriver of the pair computes the label combine ----
    __threadfence();                                   // release our stores
    __syncthreads();
    if (tid == 0) s_old = atomicAdd(&g_flag[pair], 1u);
    __syncthreads();
    if (s_old == 0) return;                            // first arriver exits
    __threadfence();                                   // acquire other side's stores

    // stage label weights into SMEM (table region is free now)
    for (int i = tid; i < 320; i += 256) {
        ((u64*)sw)[i]       = ((const u64*)g_Alab)[i];
        ((u64*)sw)[320 + i] = ((const u64*)g_Clab)[i];
    }
    __syncthreads();
    const u64* sA = (const u64*)sw;
    const u64* sC = sA + 320;

    const float* other = isLeft ? g_u : g_vleft;
    float oo[8];
    {
        const float4* s0 = (const float4*)(other + r * 8);
        float4 a = s0[0], b = s0[1];
        oo[0]=a.x; oo[1]=a.y; oo[2]=a.z; oo[3]=a.w;
        oo[4]=b.x; oo[5]=b.y; oo[6]=b.z; oo[7]=b.w;
    }
    const float pl = px[LABEL];
    if (isLeft) label_row(sA, sC, v, oo, pl, out, r);
    else        label_row(sA, sC, oo, v, pl, out, r);
}

// ---------------- launcher ----------------
extern "C" void kernel_launch(void* const* d_in, const int* in_sizes, int n_in,
                              void* d_out, int out_size) {
    const float* x      = (const float*)d_in[0];
    const float* w0     = (const float*)d_in[1];
    const float* Wleft  = (const float*)d_in[2];
    const float* wlabel = (const float*)d_in[3];
    const float* Wright = (const float*)d_in[4];
    const float* wlast  = (const float*)d_in[5];
    float* out = (float*)d_out;

    const int chainSmem = LLEFT * 128 * (int)sizeof(float);   // 200192 B
    cudaFuncSetAttribute(chain_kernel, cudaFuncAttributeMaxDynamicSharedMemorySize, chainSmem);

    const int prepN = LLEFT * 64 + LRIGHT * 64 + DD * DD * OO + 8 + 8 + NPAIR;
    prep_weights<<<(prepN + 255) / 256, 256>>>(Wleft, wlabel, Wright, w0, wlast);
    chain_kernel<<<2 * NPAIR, 256, chainSmem>>>(x, out);
}

// round 11
// speedup vs baseline: 1.3390x; 1.3390x over previous
#include <cuda_runtime.h>

#define BB      16384
#define NSITES  784
#define DD      8
#define OO      10
#define LABEL   392
#define LLEFT   391   // sites 1..391
#define LRIGHT  390   // sites 393..782 (walked reversed, transposed)
#define NPAIR   74    // CTAs per side
#define NTHR    112   // threads per CTA (3.5 warps)

typedef unsigned long long u64;

// ---------------- packed f32x2 helpers ----------------
__device__ __forceinline__ u64 pk2(float a, float b) {
    u64 r; asm("mov.b64 %0, {%1, %2};" : "=l"(r) : "f"(a), "f"(b)); return r;
}
__device__ __forceinline__ void upk2(float& a, float& b, u64 r) {
    asm("mov.b64 {%0, %1}, %2;" : "=f"(a), "=f"(b) : "l"(r));
}
__device__ __forceinline__ u64 fma2(u64 a, u64 b, u64 c) {
    u64 d; asm("fma.rn.f32x2 %0, %1, %2, %3;" : "=l"(d) : "l"(a), "l"(b), "l"(c)); return d;
}
__device__ __forceinline__ u64 mul2(u64 a, u64 b) {
    u64 d; asm("mul.rn.f32x2 %0, %1, %2;" : "=l"(d) : "l"(a), "l"(b)); return d;
}

// ---------------- scratch ----------------
__device__ __align__(16) float g_WL[LLEFT * 128];     // per step: A (64) | C (64)
__device__ __align__(16) float g_WR[LRIGHT * 128];    // transposed + reversed
__device__ __align__(8)  float g_Alab[DD * DD * OO];
__device__ __align__(8)  float g_Clab[DD * DD * OO];
__device__ float g_w0c[16];
__device__ float g_wlastc[16];
__device__ __align__(16) float g_vleft[BB * 8];
__device__ __align__(16) float g_u[BB * 8];
__device__ unsigned g_flag[NPAIR];

// ---------------- weight prep ----------------
__global__ void prep_weights(const float* __restrict__ wl,
                             const float* __restrict__ wlab,
                             const float* __restrict__ wr,
                             const float* __restrict__ w0,
                             const float* __restrict__ wlast) {
    int idx = blockIdx.x * blockDim.x + threadIdx.x;
    if (idx < LLEFT * 64) {
        int s = idx >> 6; int r = idx & 63; int d = r >> 3; int e = r & 7;
        float a = wl[((s * 8 + d) * 2 + 0) * 8 + e];
        float b = wl[((s * 8 + d) * 2 + 1) * 8 + e];
        g_WL[s * 128 + d * 8 + e] = a;
        g_WL[s * 128 + 64 + d * 8 + e] = b - a;
        return;
    }
    idx -= LLEFT * 64;
    if (idx < LRIGHT * 64) {           // step t uses site (782 - t), transposed
        int t = idx >> 6; int r = idx & 63; int i = r >> 3; int j = r & 7;
        int site_local = (LRIGHT - 1) - t;
        float a = wr[((site_local * 8 + j) * 2 + 0) * 8 + i];
        float b = wr[((site_local * 8 + j) * 2 + 1) * 8 + i];
        g_WR[t * 128 + i * 8 + j] = a;
        g_WR[t * 128 + 64 + i * 8 + j] = b - a;
        return;
    }
    idx -= LRIGHT * 64;
    if (idx < DD * DD * OO) {
        int o = idx % OO; int de = idx / OO; int e = de & 7; int d = de >> 3;
        float a = wlab[((d * 2 + 0) * 8 + e) * OO + o];
        float b = wlab[((d * 2 + 1) * 8 + e) * OO + o];
        g_Alab[(d * 8 + e) * OO + o] = a;
        g_Clab[(d * 8 + e) * OO + o] = b - a;
        return;
    }
    idx -= DD * DD * OO;
    if (idx < 8) { g_w0c[idx] = w0[idx]; g_w0c[8 + idx] = w0[8 + idx] - w0[idx]; return; }
    idx -= 8;
    if (idx < 8) {
        g_wlastc[idx]     = wlast[idx * 2 + 0];
        g_wlastc[8 + idx] = wlast[idx * 2 + 1] - wlast[idx * 2 + 0];
        return;
    }
    idx -= 8;
    if (idx < NPAIR) g_flag[idx] = 0;
}

// ---------------- one site step for 2 rows (mul2-init, no zero MOVs) ----------------
__device__ __forceinline__ void site_step(const float* __restrict__ wsite,
                                          float (&v0)[8], float (&v1)[8],
                                          float pc0, float pc1) {
    const ulonglong2* __restrict__ w2 = (const ulonglong2*)wsite;
    u64 A0, A1, A2, A3, C0, C1, C2, C3;
    u64 B0, B1, B2, B3, D0, D1, D2, D3;
    {
        u64 vd0 = pk2(v0[0], v0[0]);
        u64 vd1 = pk2(v1[0], v1[0]);
        ulonglong2 qa = w2[0],  qb = w2[1];
        ulonglong2 qc = w2[16], qd = w2[17];
        A0 = mul2(vd0, qa.x); A1 = mul2(vd0, qa.y);
        A2 = mul2(vd0, qb.x); A3 = mul2(vd0, qb.y);
        C0 = mul2(vd0, qc.x); C1 = mul2(vd0, qc.y);
        C2 = mul2(vd0, qd.x); C3 = mul2(vd0, qd.y);
        B0 = mul2(vd1, qa.x); B1 = mul2(vd1, qa.y);
        B2 = mul2(vd1, qb.x); B3 = mul2(vd1, qb.y);
        D0 = mul2(vd1, qc.x); D1 = mul2(vd1, qc.y);
        D2 = mul2(vd1, qd.x); D3 = mul2(vd1, qd.y);
    }
    #pragma unroll
    for (int i = 1; i < 8; i++) {
        u64 vd0 = pk2(v0[i], v0[i]);
        u64 vd1 = pk2(v1[i], v1[i]);
        ulonglong2 qa = w2[2*i],    qb = w2[2*i+1];
        ulonglong2 qc = w2[16+2*i], qd = w2[16+2*i+1];
        A0 = fma2(vd0, qa.x, A0); A1 = fma2(vd0, qa.y, A1);
        A2 = fma2(vd0, qb.x, A2); A3 = fma2(vd0, qb.y, A3);
        C0 = fma2(vd0, qc.x, C0); C1 = fma2(vd0, qc.y, C1);
        C2 = fma2(vd0, qd.x, C2); C3 = fma2(vd0, qd.y, C3);
        B0 = fma2(vd1, qa.x, B0); B1 = fma2(vd1, qa.y, B1);
        B2 = fma2(vd1, qb.x, B2); B3 = fma2(vd1, qb.y, B3);
        D0 = fma2(vd1, qc.x, D0); D1 = fma2(vd1, qc.y, D1);
        D2 = fma2(vd1, qd.x, D2); D3 = fma2(vd1, qd.y, D3);
    }
    u64 p20 = pk2(pc0, pc0), p21 = pk2(pc1, pc1);
    A0 = fma2(p20, C0, A0); A1 = fma2(p20, C1, A1);
    A2 = fma2(p20, C2, A2); A3 = fma2(p20, C3, A3);
    B0 = fma2(p21, D0, B0); B1 = fma2(p21, D1, B1);
    B2 = fma2(p21, D2, B2); B3 = fma2(p21, D3, B3);
    upk2(v0[0], v0[1], A0); upk2(v0[2], v0[3], A1);
    upk2(v0[4], v0[5], A2); upk2(v0[6], v0[7], A3);
    upk2(v1[0], v1[1], B0); upk2(v1[2], v1[3], B1);
    upk2(v1[4], v1[5], B2); upk2(v1[6], v1[7], B3);
}

// ---------------- label combine for one row ----------------
__device__ __forceinline__ void label_row(const u64* __restrict__ sA,
                                          const u64* __restrict__ sC,
                                          const float (&vl)[8], const float (&uu)[8],
                                          float p, float* __restrict__ out, int row) {
    const u64 p2 = pk2(p, p);
    u64 acc[5] = {0, 0, 0, 0, 0};
    #pragma unroll
    for (int d = 0; d < 8; d++) {
        #pragma unroll
        for (int e = 0; e < 8; e++) {
            const float g = vl[d] * uu[e];
            const u64 g2 = pk2(g, g);
            const u64 gp2 = mul2(g2, p2);
            const int base = (d * 8 + e) * 5;
            #pragma unroll
            for (int k = 0; k < 5; k++) {
                acc[k] = fma2(g2, sA[base + k], acc[k]);
                acc[k] = fma2(gp2, sC[base + k], acc[k]);
            }
        }
    }
    float2* o2 = (float2*)(out + row * OO);
    #pragma unroll
    for (int k = 0; k < 5; k++) {
        float lo, hi; upk2(lo, hi, acc[k]);
        o2[k] = make_float2(lo, hi);
    }
}

// ---------------- fused chain + label: 148 CTAs x 112 thr x 2 rows ----------------
__global__ __launch_bounds__(NTHR, 1) void chain_kernel(const float* __restrict__ x,
                                                        float* __restrict__ out) {
    extern __shared__ float sw[];
    __shared__ unsigned s_old;
    const int tid = threadIdx.x;
    const int blk = blockIdx.x;            // 0..147
    const bool isLeft = blk < NPAIR;
    const int pair = isLeft ? blk : blk - NPAIR;

    {   // stage this side's weights
        const float4* g4 = (const float4*)(isLeft ? g_WL : g_WR);
        float4* s4 = (float4*)sw;
        const int n4 = (isLeft ? LLEFT : LRIGHT) * 32;
        for (int i = tid; i < n4; i += NTHR) s4[i] = g4[i];
    }
    __syncthreads();

    // slot -> row pair: 74*112 = 8288 slots, rows = 2*slot clamped to 16382
    // (tail slots 8192..8287 duplicate rows 16382/16383; identical redundant writes)
    const int slot = pair * NTHR + tid;
    int r0 = slot * 2;
    if (r0 > BB - 2) r0 = BB - 2;
    const int r1 = r0 + 1;
    const float* px0 = x + (size_t)r0 * NSITES;
    const float* px1 = x + (size_t)r1 * NSITES;

    float v0[8], v1[8];
    if (isLeft) {
        float4 f0 = *(const float4*)(px0);
        float4 f1 = *(const float4*)(px1);
        #pragma unroll
        for (int d = 0; d < 8; d++) {
            v0[d] = fmaf(f0.x, g_w0c[8 + d], g_w0c[d]);
            v1[d] = fmaf(f1.x, g_w0c[8 + d], g_w0c[d]);
        }
        float4 n0 = *(const float4*)(px0 + 4);
        float4 n1 = *(const float4*)(px1 + 4);
        site_step(sw + 0 * 128, v0, v1, f0.y, f1.y);   // site 1
        site_step(sw + 1 * 128, v0, v1, f0.z, f1.z);   // site 2
        site_step(sw + 2 * 128, v0, v1, f0.w, f1.w);   // site 3
        const float* wp = sw + 3 * 128;
        #pragma unroll 1
        for (int g = 1; g <= 97; g++) {                // sites 4g..4g+3
            f0 = n0; f1 = n1;
            n0 = *(const float4*)(px0 + 4 * g + 4);    // g=97 -> x[392..395], valid
            n1 = *(const float4*)(px1 + 4 * g + 4);
            site_step(wp, v0, v1, f0.x, f1.x); wp += 128;
            site_step(wp, v0, v1, f0.y, f1.y); wp += 128;
            site_step(wp, v0, v1, f0.z, f1.z); wp += 128;
            site_step(wp, v0, v1, f0.w, f1.w); wp += 128;
        }
        float4* d0 = (float4*)(g_vleft + r0 * 8);
        d0[0] = make_float4(v0[0], v0[1], v0[2], v0[3]);
        d0[1] = make_float4(v0[4], v0[5], v0[6], v0[7]);
        float4* d1 = (float4*)(g_vleft + r1 * 8);
        d1[0] = make_float4(v1[0], v1[1], v1[2], v1[3]);
        d1[1] = make_float4(v1[4], v1[5], v1[6], v1[7]);
    } else {
        float4 f0 = *(const float4*)(px0 + 780);       // sites 780..783
        float4 f1 = *(const float4*)(px1 + 780);
        #pragma unroll
        for (int d = 0; d < 8; d++) {
            v0[d] = fmaf(f0.w, g_wlastc[8 + d], g_wlastc[d]);
            v1[d] = fmaf(f1.w, g_wlastc[8 + d], g_wlastc[d]);
        }
        float4 n0 = *(const float4*)(px0 + 776);
        float4 n1 = *(const float4*)(px1 + 776);
        site_step(sw + 0 * 128, v0, v1, f0.z, f1.z);   // site 782
        site_step(sw + 1 * 128, v0, v1, f0.y, f1.y);   // site 781
        site_step(sw + 2 * 128, v0, v1, f0.x, f1.x);   // site 780
        const float* wp = sw + 3 * 128;
        #pragma unroll 1
        for (int m = 0; m < 96; m++) {                 // sites 779-4m .. 776-4m
            f0 = n0; f1 = n1;
            n0 = *(const float4*)(px0 + 772 - 4 * m);  // m=95 -> x[392..395]; never OOB
            n1 = *(const float4*)(px1 + 772 - 4 * m);
            site_step(wp, v0, v1, f0.w, f1.w); wp += 128;
            site_step(wp, v0, v1, f0.z, f1.z); wp += 128;
            site_step(wp, v0, v1, f0.y, f1.y); wp += 128;
            site_step(wp, v0, v1, f0.x, f1.x); wp += 128;
        }
        f0 = n0; f1 = n1;                              // x[392..395]: sites 395,394,393
        site_step(wp, v0, v1, f0.w, f1.w); wp += 128;
        site_step(wp, v0, v1, f0.z, f1.z); wp += 128;
        site_step(wp, v0, v1, f0.y, f1.y);
        float4* d0 = (float4*)(g_u + r0 * 8);
        d0[0] = make_float4(v0[0], v0[1], v0[2], v0[3]);
        d0[1] = make_float4(v0[4], v0[5], v0[6], v0[7]);
        float4* d1 = (float4*)(g_u + r1 * 8);
        d1[0] = make_float4(v1[0], v1[1], v1[2], v1[3]);
        d1[1] = make_float4(v1[4], v1[5], v1[6], v1[7]);
    }

    // ---- handoff: second arriver of the pair computes the label combine ----
    __threadfence();                                   // release our stores
    __syncthreads();
    if (tid == 0) s_old = atomicAdd(&g_flag[pair], 1u);
    __syncthreads();
    if (!(s_old & 1)) return;                          // first arriver exits
    __threadfence();                                   // acquire other side's stores

    // stage label weights into SMEM (table region is free now)
    for (int i = tid; i < 320; i += NTHR) {
        ((u64*)sw)[i]       = ((const u64*)g_Alab)[i];
        ((u64*)sw)[320 + i] = ((const u64*)g_Clab)[i];
    }
    __syncthreads();
    const u64* sA = (const u64*)sw;
    const u64* sC = sA + 320;

    const float* other = isLeft ? g_u : g_vleft;
    #pragma unroll 1
    for (int rr = 0; rr < 2; rr++) {
        const int row = rr == 0 ? r0 : r1;
        float vv[8], oo[8];
        #pragma unroll
        for (int e = 0; e < 8; e++) vv[e] = (rr == 0) ? v0[e] : v1[e];
        const float4* s0 = (const float4*)(other + row * 8);
        float4 a = s0[0], b = s0[1];
        oo[0]=a.x; oo[1]=a.y; oo[2]=a.z; oo[3]=a.w;
        oo[4]=b.x; oo[5]=b.y; oo[6]=b.z; oo[7]=b.w;
        const float pl = x[(size_t)row * NSITES + LABEL];
        if (isLeft) label_row(sA, sC, vv, oo, pl, out, row);
        else        label_row(sA, sC, oo, vv, pl, out, row);
    }
}

// ---------------- launcher ----------------
extern "C" void kernel_launch(void* const* d_in, const int* in_sizes, int n_in,
                              void* d_out, int out_size) {
    const float* x      = (const float*)d_in[0];
    const float* w0     = (const float*)d_in[1];
    const float* Wleft  = (const float*)d_in[2];
    const float* wlabel = (const float*)d_in[3];
    const float* Wright = (const float*)d_in[4];
    const float* wlast  = (const float*)d_in[5];
    float* out = (float*)d_out;

    const int chainSmem = LLEFT * 128 * (int)sizeof(float);   // 200192 B
    cudaFuncSetAttribute(chain_kernel, cudaFuncAttributeMaxDynamicSharedMemorySize, chainSmem);

    const int prepN = LLEFT * 64 + LRIGHT * 64 + DD * DD * OO + 8 + 8 + NPAIR;
    prep_weights<<<(prepN + 255) / 256, 256>>>(Wleft, wlabel, Wright, w0, wlast);
    chain_kernel<<<2 * NPAIR, NTHR, chainSmem>>>(x, out);
}